// round 7
// baseline (speedup 1.0000x reference)
#include <cuda_runtime.h>

#define NB 4
#define DK 256
#define DV 516
#define HW 4096
#define LM 32
#define DS 4            // d-splits inside attn block
#define DQ 4            // d-splits across gridDim.y (64 d per block)

// temp = log2(32*64*64 + 64*64) / sqrt(256)
#define TEMP 1.06527463f

// Scratch (static device allocations only; no cudaMalloc anywhere)
__device__ float g_q[NB * DK * HW];            // 16 MB: q[b][d][hw], pre-scaled
__device__ float g_attn[NB * LM * HW];         // 2 MB:  attn[b][m][hw]
__device__ float g_part[DQ * NB * LM * HW];    // 8 MB:  partial scores

// ---------------------------------------------------------------------------
// Kernel 1: q[b][d][hw] = TEMP * sum_c Q[c][d] * fc[b][c][hw]
// 128x128 block tile, BK=8, 256 threads, 8x8 register tile, double-buffered
// smem with register prefetch -> one __syncthreads per k-tile.
// ---------------------------------------------------------------------------
__global__ __launch_bounds__(256) void qproj_kernel(
    const float* __restrict__ fc, const float* __restrict__ Qm) {
    __shared__ float As[2][8][128];   // [buf][c][d]
    __shared__ float Bs[2][8][128];   // [buf][c][hw]

    const int b   = blockIdx.z;
    const int d0  = blockIdx.y * 128;
    const int hw0 = blockIdx.x * 128;
    const int tid = threadIdx.x;
    const int tx  = tid & 15;        // hw tile coord (x8)
    const int ty  = tid >> 4;        // d  tile coord (x8)

    const float* fcb = fc + (size_t)b * DK * HW;

    const int lr = tid >> 5;          // 0..7  (c within tile)
    const int lc = (tid & 31) * 4;    // 0..124

    float acc[8][8];
#pragma unroll
    for (int i = 0; i < 8; i++)
#pragma unroll
        for (int j = 0; j < 8; j++) acc[i][j] = 0.0f;

    float4 pa = *(const float4*)(Qm + (size_t)lr * DK + d0 + lc);
    float4 pb = *(const float4*)(fcb + (size_t)lr * HW + hw0 + lc);
    *(float4*)&As[0][lr][lc] = pa;
    *(float4*)&Bs[0][lr][lc] = pb;
    __syncthreads();

    int buf = 0;
    for (int k0 = 0; k0 < DK; k0 += 8) {
        const bool has_next = (k0 + 8) < DK;
        if (has_next) {
            pa = *(const float4*)(Qm + (size_t)(k0 + 8 + lr) * DK + d0 + lc);
            pb = *(const float4*)(fcb + (size_t)(k0 + 8 + lr) * HW + hw0 + lc);
        }

#pragma unroll
        for (int k = 0; k < 8; k++) {
            float a[8], bb[8];
            *(float4*)(a)      = *(const float4*)&As[buf][k][ty * 8];
            *(float4*)(a + 4)  = *(const float4*)&As[buf][k][ty * 8 + 4];
            *(float4*)(bb)     = *(const float4*)&Bs[buf][k][tx * 8];
            *(float4*)(bb + 4) = *(const float4*)&Bs[buf][k][tx * 8 + 4];
#pragma unroll
            for (int i = 0; i < 8; i++)
#pragma unroll
                for (int j = 0; j < 8; j++) acc[i][j] += a[i] * bb[j];
        }

        if (has_next) {
            *(float4*)&As[buf ^ 1][lr][lc] = pa;
            *(float4*)&Bs[buf ^ 1][lr][lc] = pb;
            __syncthreads();
            buf ^= 1;
        }
    }

    float* qo = g_q + (size_t)b * DK * HW;
#pragma unroll
    for (int i = 0; i < 8; i++) {
        float* dst = qo + (size_t)(d0 + ty * 8 + i) * HW + hw0 + tx * 8;
        float4 v0, v1;
        v0.x = acc[i][0] * TEMP; v0.y = acc[i][1] * TEMP;
        v0.z = acc[i][2] * TEMP; v0.w = acc[i][3] * TEMP;
        v1.x = acc[i][4] * TEMP; v1.y = acc[i][5] * TEMP;
        v1.z = acc[i][6] * TEMP; v1.w = acc[i][7] * TEMP;
        *(float4*)(dst)     = v0;
        *(float4*)(dst + 4) = v1;
    }
}

// ---------------------------------------------------------------------------
// Kernel 2a: partial scores. Grid (HW/32, DQ) = 512 blocks (full chip).
// Block 512 = 32 hw lanes x 4 ms (8 m each) x 4 ds (16 d each). Each thread
// computes all 4 batches (key element loaded ONCE; 128B coalesced loads).
// result -> g_part[dq][b][m][hw].
// ---------------------------------------------------------------------------
extern __shared__ float s_red[];   // [DS][LM][NB][32] = 64KB

__global__ __launch_bounds__(512) void attn_partial_kernel(
    const float* __restrict__ key) {
    const int tid  = threadIdx.x;
    const int lane = tid & 31;           // hw
    const int ms   = (tid >> 5) & 3;     // m group (8 m)
    const int ds   = tid >> 7;           // d sub-split (16 d each)
    const int hw   = blockIdx.x * 32 + lane;
    const int dq   = blockIdx.y;
    const int dbase = dq * 64 + ds * 16;

    const float* qp[NB];
#pragma unroll
    for (int b = 0; b < NB; b++)
        qp[b] = g_q + (size_t)b * DK * HW + (size_t)dbase * HW + hw;
    const float* kp[8];
#pragma unroll
    for (int j = 0; j < 8; j++)
        kp[j] = key + (size_t)(ms * 8 + j) * DK * HW + (size_t)dbase * HW + hw;

    float acc[NB][8];
#pragma unroll
    for (int b = 0; b < NB; b++)
#pragma unroll
        for (int j = 0; j < 8; j++) acc[b][j] = 0.0f;

#pragma unroll 2
    for (int d = 0; d < 16; d++) {
        float q0 = qp[0][0], q1 = qp[1][0], q2 = qp[2][0], q3 = qp[3][0];
#pragma unroll
        for (int j = 0; j < 8; j++) {
            const float kv = kp[j][0];
            acc[0][j] += q0 * kv;
            acc[1][j] += q1 * kv;
            acc[2][j] += q2 * kv;
            acc[3][j] += q3 * kv;
        }
#pragma unroll
        for (int b = 0; b < NB; b++) qp[b] += HW;
#pragma unroll
        for (int j = 0; j < 8; j++) kp[j] += HW;
    }

    // stash partials: s_red[ds][m][b][lane]
#pragma unroll
    for (int b = 0; b < NB; b++)
#pragma unroll
        for (int j = 0; j < 8; j++)
            s_red[(((ds * LM) + ms * 8 + j) * NB + b) * 32 + lane] = acc[b][j];
    __syncthreads();

    // reduce ds and write partial: 128 threads = 32 hw x 4 b
    if (tid < 128) {
        const int b   = tid >> 5;
        const int l   = tid & 31;
        const int hwg = blockIdx.x * 32 + l;
        float* pp = g_part + (((size_t)dq * NB + b) * LM) * HW + hwg;
#pragma unroll
        for (int m = 0; m < LM; m++) {
            const float v = s_red[((0 * LM + m) * NB + b) * 32 + l]
                          + s_red[((1 * LM + m) * NB + b) * 32 + l]
                          + s_red[((2 * LM + m) * NB + b) * 32 + l]
                          + s_red[((3 * LM + m) * NB + b) * 32 + l];
            pp[(size_t)m * HW] = v;
        }
    }
}

// ---------------------------------------------------------------------------
// Kernel 2b: finish — sum DQ partials, softmax over m, write g_attn.
// Block 128 = 32 hw x 4 b, grid 128.
// ---------------------------------------------------------------------------
__global__ __launch_bounds__(128) void attn_finish_kernel() {
    const int tid = threadIdx.x;
    const int b   = tid >> 5;
    const int l   = tid & 31;
    const int hw  = blockIdx.x * 32 + l;

    float s[LM];
    float mx = -1e30f;
#pragma unroll
    for (int m = 0; m < LM; m++) {
        float v = 0.0f;
#pragma unroll
        for (int dq = 0; dq < DQ; dq++)
            v += g_part[((((size_t)dq * NB + b) * LM) + m) * HW + hw];
        s[m] = v;
        mx = fmaxf(mx, v);
    }
    float sum = 0.0f;
#pragma unroll
    for (int m = 0; m < LM; m++) { s[m] = __expf(s[m] - mx); sum += s[m]; }
    const float inv = 1.0f / sum;
    float* ap = g_attn + (size_t)b * LM * HW + hw;
#pragma unroll
    for (int m = 0; m < LM; m++) ap[(size_t)m * HW] = s[m] * inv;
}

// ---------------------------------------------------------------------------
// Kernel 3: out[b][c][hw] = fm[b][c][hw] + 0.5*sum_m attn[b][m][hw]*val[m][c][hw]
// v3: smem-staged attn + float4 + ONE batch per thread + register cap.
// __launch_bounds__(256, 3) caps regs at ~84 so ptxas schedules val loads in
// waves instead of hoarding the register file (R6 failure mode: regs=255).
// Block 256 = 8 warps: warp&3 = batch, warp>>2 = c-half of a 43-wide c-chunk.
// One warp spans 128 hw (32 lanes x float4); the 4 batch warps hit identical
// val lines (L1). Occupancy: smem-limited 3 blocks/SM = 24 warps (37.5%).
// Grid (32 hw-tiles, 12 c-chunks).
// ---------------------------------------------------------------------------
__global__ __launch_bounds__(256, 3) void out_kernel(
    const float* __restrict__ fm, const float* __restrict__ val,
    float* __restrict__ out) {
    __shared__ float a_s[NB][LM][128];   // 64KB

    const int tid  = threadIdx.x;
    const int lane = tid & 31;
    const int wid  = tid >> 5;
    const int b    = wid & 3;
    const int ch   = wid >> 2;              // c-half: 0 -> 22 c's, 1 -> 21 c's
    const int hw0  = blockIdx.x * 128;
    const int c0   = blockIdx.y * 43;       // 516 = 12 * 43

    // stage attn tile: [4b][32m][128hw] — coalesced float4 fill (16 per thread)
    {
        const float* gsrc = g_attn + hw0;
        for (int i = tid; i < NB * LM * 32; i += 256) {
            const int l4  = i & 31;            // float4 index within 128 hw
            const int m   = (i >> 5) & 31;
            const int bb  = i >> 10;
            *(float4*)&a_s[bb][m][l4 * 4] =
                *(const float4*)(gsrc + ((size_t)bb * LM + m) * HW + l4 * 4);
        }
    }
    __syncthreads();

    const int cbeg = c0 + (ch ? 22 : 0);
    const int cend = c0 + (ch ? 43 : 22);

    const float* fmp = fm + (size_t)b * DV * HW + hw0 + lane * 4;
    float*       op  = out + (size_t)b * DV * HW + hw0 + lane * 4;
    const float* asb = &a_s[b][0][lane * 4];

    for (int c = cbeg; c < cend; c++) {
        const float* vp = val + (size_t)c * HW + hw0 + lane * 4;
        float4 acc0 = make_float4(0.f, 0.f, 0.f, 0.f);
        float4 acc1 = make_float4(0.f, 0.f, 0.f, 0.f);
#pragma unroll
        for (int m = 0; m < LM; m += 2) {
            const float4 v0 = *(const float4*)(vp + (size_t)m * DV * HW);
            const float4 a0 = *(const float4*)(asb + m * 128);
            acc0.x += a0.x * v0.x;
            acc0.y += a0.y * v0.y;
            acc0.z += a0.z * v0.z;
            acc0.w += a0.w * v0.w;
            const float4 v1 = *(const float4*)(vp + (size_t)(m + 1) * DV * HW);
            const float4 a1 = *(const float4*)(asb + (m + 1) * 128);
            acc1.x += a1.x * v1.x;
            acc1.y += a1.y * v1.y;
            acc1.z += a1.z * v1.z;
            acc1.w += a1.w * v1.w;
        }
        const float4 f = *(const float4*)(fmp + (size_t)c * HW);
        float4 o;
        o.x = f.x + 0.5f * (acc0.x + acc1.x);
        o.y = f.y + 0.5f * (acc0.y + acc1.y);
        o.z = f.z + 0.5f * (acc0.z + acc1.z);
        o.w = f.w + 0.5f * (acc0.w + acc1.w);
        *(float4*)(op + (size_t)c * HW) = o;
    }
}

// ---------------------------------------------------------------------------
// Launch. Inputs (metadata order): fc, fm, key_buffer, value_buffer, Q, K, V.
// concat(new, buffer)[-32:] keeps exactly the buffers -> K and V matrices are
// dead inputs; only q = fc@Q survives.
// ---------------------------------------------------------------------------
extern "C" void kernel_launch(void* const* d_in, const int* in_sizes, int n_in,
                              void* d_out, int out_size) {
    const float* fc   = (const float*)d_in[0];
    const float* fm   = (const float*)d_in[1];
    const float* keyb = (const float*)d_in[2];
    const float* valb = (const float*)d_in[3];
    const float* Qm   = (const float*)d_in[4];
    float* out = (float*)d_out;

    const int red_bytes = DS * LM * NB * 32 * sizeof(float);   // 64KB
    cudaFuncSetAttribute(attn_partial_kernel,
                         cudaFuncAttributeMaxDynamicSharedMemorySize, red_bytes);

    qproj_kernel<<<dim3(HW / 128, DK / 128, NB), 256>>>(fc, Qm);
    attn_partial_kernel<<<dim3(HW / 32, DQ), 512, red_bytes>>>(keyb);
    attn_finish_kernel<<<dim3(HW / 32), 128>>>();
    out_kernel<<<dim3(HW / 128, 12), 256>>>(fm, valb, out);
}

// round 8
// speedup vs baseline: 1.3682x; 1.3682x over previous
#include <cuda_runtime.h>

#define NB 4
#define DK 256
#define DV 516
#define HW 4096
#define LM 32
#define DS 4            // d-splits inside attn block
#define DQ 4            // d-splits across gridDim.y (64 d per block)

// temp = log2(32*64*64 + 64*64) / sqrt(256)
#define TEMP 1.06527463f

// Scratch (static device allocations only; no cudaMalloc anywhere)
__device__ float g_q[NB * DK * HW];            // 16 MB: q[b][d][hw], pre-scaled
__device__ float g_attn[NB * LM * HW];         // 2 MB:  attn[b][m][hw]
__device__ float g_part[DQ * NB * LM * HW];    // 8 MB:  partial scores

// ---------------------------------------------------------------------------
// Kernel 1: q[b][d][hw] = TEMP * sum_c Q[c][d] * fc[b][c][hw]
// 128x128 block tile, BK=8, 256 threads, 8x8 register tile, double-buffered
// smem AND double-buffered register fragments: frag[k+1] loads issue before
// frag[k]'s FFMAs, breaking the LDS->FFMA short-scoreboard stall.
// __launch_bounds__(256,2) caps regs at 128 to keep 2 blocks/SM.
// ---------------------------------------------------------------------------
__global__ __launch_bounds__(256, 2) void qproj_kernel(
    const float* __restrict__ fc, const float* __restrict__ Qm) {
    __shared__ float As[2][8][128];   // [buf][c][d]
    __shared__ float Bs[2][8][128];   // [buf][c][hw]

    const int b   = blockIdx.z;
    const int d0  = blockIdx.y * 128;
    const int hw0 = blockIdx.x * 128;
    const int tid = threadIdx.x;
    const int tx  = tid & 15;        // hw tile coord (x8)
    const int ty  = tid >> 4;        // d  tile coord (x8)

    const float* fcb = fc + (size_t)b * DK * HW;

    const int lr = tid >> 5;          // 0..7  (c within tile)
    const int lc = (tid & 31) * 4;    // 0..124

    float acc[8][8];
#pragma unroll
    for (int i = 0; i < 8; i++)
#pragma unroll
        for (int j = 0; j < 8; j++) acc[i][j] = 0.0f;

    float4 pa = *(const float4*)(Qm + (size_t)lr * DK + d0 + lc);
    float4 pb = *(const float4*)(fcb + (size_t)lr * HW + hw0 + lc);
    *(float4*)&As[0][lr][lc] = pa;
    *(float4*)&Bs[0][lr][lc] = pb;
    __syncthreads();

    // register fragment double buffer
    float fa[2][8], fb[2][8];

    int buf = 0;
    for (int k0 = 0; k0 < DK; k0 += 8) {
        const bool has_next = (k0 + 8) < DK;
        if (has_next) {
            pa = *(const float4*)(Qm + (size_t)(k0 + 8 + lr) * DK + d0 + lc);
            pb = *(const float4*)(fcb + (size_t)(k0 + 8 + lr) * HW + hw0 + lc);
        }

        // preload fragment k=0 of this tile
        *(float4*)(fa[0])     = *(const float4*)&As[buf][0][ty * 8];
        *(float4*)(fa[0] + 4) = *(const float4*)&As[buf][0][ty * 8 + 4];
        *(float4*)(fb[0])     = *(const float4*)&Bs[buf][0][tx * 8];
        *(float4*)(fb[0] + 4) = *(const float4*)&Bs[buf][0][tx * 8 + 4];

#pragma unroll
        for (int k = 0; k < 8; k++) {
            const int cur = k & 1;
            const int nxt = cur ^ 1;
            if (k < 7) {   // issue next fragment's LDS before this k's FFMAs
                *(float4*)(fa[nxt])     = *(const float4*)&As[buf][k + 1][ty * 8];
                *(float4*)(fa[nxt] + 4) = *(const float4*)&As[buf][k + 1][ty * 8 + 4];
                *(float4*)(fb[nxt])     = *(const float4*)&Bs[buf][k + 1][tx * 8];
                *(float4*)(fb[nxt] + 4) = *(const float4*)&Bs[buf][k + 1][tx * 8 + 4];
            }
#pragma unroll
            for (int i = 0; i < 8; i++)
#pragma unroll
                for (int j = 0; j < 8; j++)
                    acc[i][j] += fa[cur][i] * fb[cur][j];
        }

        if (has_next) {
            *(float4*)&As[buf ^ 1][lr][lc] = pa;
            *(float4*)&Bs[buf ^ 1][lr][lc] = pb;
            __syncthreads();
            buf ^= 1;
        }
    }

    float* qo = g_q + (size_t)b * DK * HW;
#pragma unroll
    for (int i = 0; i < 8; i++) {
        float* dst = qo + (size_t)(d0 + ty * 8 + i) * HW + hw0 + tx * 8;
        float4 v0, v1;
        v0.x = acc[i][0] * TEMP; v0.y = acc[i][1] * TEMP;
        v0.z = acc[i][2] * TEMP; v0.w = acc[i][3] * TEMP;
        v1.x = acc[i][4] * TEMP; v1.y = acc[i][5] * TEMP;
        v1.z = acc[i][6] * TEMP; v1.w = acc[i][7] * TEMP;
        *(float4*)(dst)     = v0;
        *(float4*)(dst + 4) = v1;
    }
}

// ---------------------------------------------------------------------------
// Kernel 2a: partial scores. Grid (HW/32, DQ) = 512 blocks (full chip).
// Block 512 = 32 hw lanes x 4 ms (8 m each) x 4 ds (16 d each). Each thread
// computes all 4 batches (key element loaded ONCE; 128B coalesced loads).
// result -> g_part[dq][b][m][hw].
// ---------------------------------------------------------------------------
extern __shared__ float s_red[];   // [DS][LM][NB][32] = 64KB

__global__ __launch_bounds__(512) void attn_partial_kernel(
    const float* __restrict__ key) {
    const int tid  = threadIdx.x;
    const int lane = tid & 31;           // hw
    const int ms   = (tid >> 5) & 3;     // m group (8 m)
    const int ds   = tid >> 7;           // d sub-split (16 d each)
    const int hw   = blockIdx.x * 32 + lane;
    const int dq   = blockIdx.y;
    const int dbase = dq * 64 + ds * 16;

    const float* qp[NB];
#pragma unroll
    for (int b = 0; b < NB; b++)
        qp[b] = g_q + (size_t)b * DK * HW + (size_t)dbase * HW + hw;
    const float* kp[8];
#pragma unroll
    for (int j = 0; j < 8; j++)
        kp[j] = key + (size_t)(ms * 8 + j) * DK * HW + (size_t)dbase * HW + hw;

    float acc[NB][8];
#pragma unroll
    for (int b = 0; b < NB; b++)
#pragma unroll
        for (int j = 0; j < 8; j++) acc[b][j] = 0.0f;

#pragma unroll 2
    for (int d = 0; d < 16; d++) {
        float q0 = qp[0][0], q1 = qp[1][0], q2 = qp[2][0], q3 = qp[3][0];
#pragma unroll
        for (int j = 0; j < 8; j++) {
            const float kv = kp[j][0];
            acc[0][j] += q0 * kv;
            acc[1][j] += q1 * kv;
            acc[2][j] += q2 * kv;
            acc[3][j] += q3 * kv;
        }
#pragma unroll
        for (int b = 0; b < NB; b++) qp[b] += HW;
#pragma unroll
        for (int j = 0; j < 8; j++) kp[j] += HW;
    }

    // stash partials: s_red[ds][m][b][lane]
#pragma unroll
    for (int b = 0; b < NB; b++)
#pragma unroll
        for (int j = 0; j < 8; j++)
            s_red[(((ds * LM) + ms * 8 + j) * NB + b) * 32 + lane] = acc[b][j];
    __syncthreads();

    // reduce ds and write partial: 128 threads = 32 hw x 4 b
    if (tid < 128) {
        const int b   = tid >> 5;
        const int l   = tid & 31;
        const int hwg = blockIdx.x * 32 + l;
        float* pp = g_part + (((size_t)dq * NB + b) * LM) * HW + hwg;
#pragma unroll
        for (int m = 0; m < LM; m++) {
            const float v = s_red[((0 * LM + m) * NB + b) * 32 + l]
                          + s_red[((1 * LM + m) * NB + b) * 32 + l]
                          + s_red[((2 * LM + m) * NB + b) * 32 + l]
                          + s_red[((3 * LM + m) * NB + b) * 32 + l];
            pp[(size_t)m * HW] = v;
        }
    }
}

// ---------------------------------------------------------------------------
// Kernel 2b: finish — sum DQ partials, softmax over m, write g_attn.
// Block 128 = 32 hw x 4 b, grid 128.
// ---------------------------------------------------------------------------
__global__ __launch_bounds__(128) void attn_finish_kernel() {
    const int tid = threadIdx.x;
    const int b   = tid >> 5;
    const int l   = tid & 31;
    const int hw  = blockIdx.x * 32 + l;

    float s[LM];
    float mx = -1e30f;
#pragma unroll
    for (int m = 0; m < LM; m++) {
        float v = 0.0f;
#pragma unroll
        for (int dq = 0; dq < DQ; dq++)
            v += g_part[((((size_t)dq * NB + b) * LM) + m) * HW + hw];
        s[m] = v;
        mx = fmaxf(mx, v);
    }
    float sum = 0.0f;
#pragma unroll
    for (int m = 0; m < LM; m++) { s[m] = __expf(s[m] - mx); sum += s[m]; }
    const float inv = 1.0f / sum;
    float* ap = g_attn + (size_t)b * LM * HW + hw;
#pragma unroll
    for (int m = 0; m < LM; m++) ap[(size_t)m * HW] = s[m] * inv;
}

// ---------------------------------------------------------------------------
// Kernel 3: out[b][c][hw] = fm[b][c][hw] + 0.5*sum_m attn[b][m][hw]*val[m][c][hw]
// EXACT R5 version (best measured: 94us, minimal DRAM traffic, 45% BW).
// Block 256 = 32 hw x 2 batch-groups x 4 hw-subtiles. Each thread handles 2
// batches (attn in 64 regs); val loaded once per pair (register-level reuse).
// Grid (32 hw-tiles, 12 c-chunks of 43).
// ---------------------------------------------------------------------------
__global__ __launch_bounds__(256) void out_kernel(
    const float* __restrict__ fm, const float* __restrict__ val,
    float* __restrict__ out) {
    const int tid  = threadIdx.x;
    const int lane = tid & 31;
    const int bg   = (tid >> 5) & 1;
    const int sub  = tid >> 6;
    const int hw   = blockIdx.x * 128 + sub * 32 + lane;
    const int c0   = blockIdx.y * 43;       // 516 = 12 * 43
    const int b0   = bg * 2;
    const int b1   = b0 + 1;

    float a0[LM], a1[LM];
    {
        const float* ap0 = g_attn + (size_t)b0 * LM * HW + hw;
        const float* ap1 = g_attn + (size_t)b1 * LM * HW + hw;
#pragma unroll
        for (int m = 0; m < LM; m++) {
            a0[m] = ap0[(size_t)m * HW];
            a1[m] = ap1[(size_t)m * HW];
        }
    }

    const float* fmp0 = fm + (size_t)b0 * DV * HW + hw;
    const float* fmp1 = fm + (size_t)b1 * DV * HW + hw;
    float*       op0  = out + (size_t)b0 * DV * HW + hw;
    float*       op1  = out + (size_t)b1 * DV * HW + hw;

#pragma unroll 2
    for (int cc = 0; cc < 43; cc++) {
        const int c = c0 + cc;
        const float* vp = val + (size_t)c * HW + hw;
        float s0 = 0.0f, s1 = 0.0f, t0 = 0.0f, t1 = 0.0f;
#pragma unroll
        for (int m = 0; m < LM; m += 2) {
            const float v0 = vp[(size_t)(m * DV) * HW];
            const float v1 = vp[(size_t)((m + 1) * DV) * HW];
            s0 += a0[m] * v0;     t0 += a1[m] * v0;
            s1 += a0[m + 1] * v1; t1 += a1[m + 1] * v1;
        }
        op0[(size_t)c * HW] = fmp0[(size_t)c * HW] + 0.5f * (s0 + s1);
        op1[(size_t)c * HW] = fmp1[(size_t)c * HW] + 0.5f * (t0 + t1);
    }
}

// ---------------------------------------------------------------------------
// Launch. Inputs (metadata order): fc, fm, key_buffer, value_buffer, Q, K, V.
// concat(new, buffer)[-32:] keeps exactly the buffers -> K and V matrices are
// dead inputs; only q = fc@Q survives.
// ---------------------------------------------------------------------------
extern "C" void kernel_launch(void* const* d_in, const int* in_sizes, int n_in,
                              void* d_out, int out_size) {
    const float* fc   = (const float*)d_in[0];
    const float* fm   = (const float*)d_in[1];
    const float* keyb = (const float*)d_in[2];
    const float* valb = (const float*)d_in[3];
    const float* Qm   = (const float*)d_in[4];
    float* out = (float*)d_out;

    const int red_bytes = DS * LM * NB * 32 * sizeof(float);   // 64KB
    cudaFuncSetAttribute(attn_partial_kernel,
                         cudaFuncAttributeMaxDynamicSharedMemorySize, red_bytes);

    qproj_kernel<<<dim3(HW / 128, DK / 128, NB), 256>>>(fc, Qm);
    attn_partial_kernel<<<dim3(HW / 32, DQ), 512, red_bytes>>>(keyb);
    attn_finish_kernel<<<dim3(HW / 32), 128>>>();
    out_kernel<<<dim3(HW / 128, 12), 256>>>(fm, valb, out);
}

// round 9
// speedup vs baseline: 1.3709x; 1.0020x over previous
#include <cuda_runtime.h>

#define NB 4
#define DK 256
#define DV 516
#define HW 4096
#define LM 32
#define DS 4            // d-splits inside attn block
#define DQ 4            // d-splits across gridDim.y (64 d per block)

// temp = log2(32*64*64 + 64*64) / sqrt(256)
#define TEMP 1.06527463f

// packed f32x2 FMA: d = a*b + d, lane-wise (2 independent IEEE fp32 fmas)
#define FMA_F32X2(d, a, b) \
    asm("fma.rn.f32x2 %0, %1, %2, %0;" : "+l"(d) : "l"(a), "l"(b))
// duplicate one fp32 into both lanes of a 64-bit packed register
#define PACK_DUP_F32X2(out, f) \
    asm("mov.b64 %0, {%1, %1};" : "=l"(out) : "r"(__float_as_uint(f)))

// Scratch (static device allocations only; no cudaMalloc anywhere)
__device__ float g_q[NB * DK * HW];            // 16 MB: q[b][d][hw], pre-scaled
__device__ float g_attn[NB * LM * HW];         // 2 MB:  attn[b][m][hw]
__device__ float g_part[DQ * NB * LM * HW];    // 8 MB:  partial scores

// ---------------------------------------------------------------------------
// Kernel 1: q[b][d][hw] = TEMP * sum_c Q[c][d] * fc[b][c][hw]
// 128x128 block tile, BK=8, 256 threads, 8x8 register tile, double-buffered
// smem + register fragments. Inner product uses PACKED fma.rn.f32x2 (FFMA2):
// the scalar-FFMA version was AT the 2-FFMA/cy/SM issue roofline; FFMA2 is the
// only path to the 2x packed peak (ptxas never auto-emits it).
// B fragments reinterpret smem float pairs as u64 directly (hw-direction
// pairs); A values dup-packed via mov.b64. Per-lane math identical IEEE fma.
// ---------------------------------------------------------------------------
__global__ __launch_bounds__(256, 2) void qproj_kernel(
    const float* __restrict__ fc, const float* __restrict__ Qm) {
    __shared__ float As[2][8][128];   // [buf][c][d]
    __shared__ float Bs[2][8][128];   // [buf][c][hw]

    const int b   = blockIdx.z;
    const int d0  = blockIdx.y * 128;
    const int hw0 = blockIdx.x * 128;
    const int tid = threadIdx.x;
    const int tx  = tid & 15;        // hw tile coord (x8)
    const int ty  = tid >> 4;        // d  tile coord (x8)

    const float* fcb = fc + (size_t)b * DK * HW;

    const int lr = tid >> 5;          // 0..7  (c within tile)
    const int lc = (tid & 31) * 4;    // 0..124

    // packed accumulators: acc2[i][j2] holds cols (tx*8+2*j2, +1) for row i
    unsigned long long acc2[8][4];
#pragma unroll
    for (int i = 0; i < 8; i++)
#pragma unroll
        for (int j = 0; j < 4; j++) acc2[i][j] = 0ull;   // {0.f, 0.f}

    float4 pa = *(const float4*)(Qm + (size_t)lr * DK + d0 + lc);
    float4 pb = *(const float4*)(fcb + (size_t)lr * HW + hw0 + lc);
    *(float4*)&As[0][lr][lc] = pa;
    *(float4*)&Bs[0][lr][lc] = pb;
    __syncthreads();

    // register fragment double buffer
    float fa[2][8];
    unsigned long long fb[2][4];

    int buf = 0;
    for (int k0 = 0; k0 < DK; k0 += 8) {
        const bool has_next = (k0 + 8) < DK;
        if (has_next) {
            pa = *(const float4*)(Qm + (size_t)(k0 + 8 + lr) * DK + d0 + lc);
            pb = *(const float4*)(fcb + (size_t)(k0 + 8 + lr) * HW + hw0 + lc);
        }

        // preload fragment k=0 of this tile
        *(float4*)(fa[0])     = *(const float4*)&As[buf][0][ty * 8];
        *(float4*)(fa[0] + 4) = *(const float4*)&As[buf][0][ty * 8 + 4];
        {
            ulonglong2 t0 = *(const ulonglong2*)&Bs[buf][0][tx * 8];
            ulonglong2 t1 = *(const ulonglong2*)&Bs[buf][0][tx * 8 + 4];
            fb[0][0] = t0.x; fb[0][1] = t0.y; fb[0][2] = t1.x; fb[0][3] = t1.y;
        }

#pragma unroll
        for (int k = 0; k < 8; k++) {
            const int cur = k & 1;
            const int nxt = cur ^ 1;
            if (k < 7) {   // issue next fragment's LDS before this k's FFMAs
                *(float4*)(fa[nxt])     = *(const float4*)&As[buf][k + 1][ty * 8];
                *(float4*)(fa[nxt] + 4) = *(const float4*)&As[buf][k + 1][ty * 8 + 4];
                ulonglong2 t0 = *(const ulonglong2*)&Bs[buf][k + 1][tx * 8];
                ulonglong2 t1 = *(const ulonglong2*)&Bs[buf][k + 1][tx * 8 + 4];
                fb[nxt][0] = t0.x; fb[nxt][1] = t0.y;
                fb[nxt][2] = t1.x; fb[nxt][3] = t1.y;
            }
#pragma unroll
            for (int i = 0; i < 8; i++) {
                unsigned long long a2;
                PACK_DUP_F32X2(a2, fa[cur][i]);
                FMA_F32X2(acc2[i][0], a2, fb[cur][0]);
                FMA_F32X2(acc2[i][1], a2, fb[cur][1]);
                FMA_F32X2(acc2[i][2], a2, fb[cur][2]);
                FMA_F32X2(acc2[i][3], a2, fb[cur][3]);
            }
        }

        if (has_next) {
            *(float4*)&As[buf ^ 1][lr][lc] = pa;
            *(float4*)&Bs[buf ^ 1][lr][lc] = pb;
            __syncthreads();
            buf ^= 1;
        }
    }

    float* qo = g_q + (size_t)b * DK * HW;
#pragma unroll
    for (int i = 0; i < 8; i++) {
        float* dst = qo + (size_t)(d0 + ty * 8 + i) * HW + hw0 + tx * 8;
        const float* af = (const float*)acc2[i];   // little-endian: low lane first
        float4 v0, v1;
        v0.x = af[0] * TEMP; v0.y = af[1] * TEMP;
        v0.z = af[2] * TEMP; v0.w = af[3] * TEMP;
        v1.x = af[4] * TEMP; v1.y = af[5] * TEMP;
        v1.z = af[6] * TEMP; v1.w = af[7] * TEMP;
        *(float4*)(dst)     = v0;
        *(float4*)(dst + 4) = v1;
    }
}

// ---------------------------------------------------------------------------
// Kernel 2a: partial scores. Grid (HW/32, DQ) = 512 blocks (full chip).
// Block 512 = 32 hw lanes x 4 ms (8 m each) x 4 ds (16 d each). Each thread
// computes all 4 batches (key element loaded ONCE; 128B coalesced loads).
// result -> g_part[dq][b][m][hw].
// ---------------------------------------------------------------------------
extern __shared__ float s_red[];   // [DS][LM][NB][32] = 64KB

__global__ __launch_bounds__(512) void attn_partial_kernel(
    const float* __restrict__ key) {
    const int tid  = threadIdx.x;
    const int lane = tid & 31;           // hw
    const int ms   = (tid >> 5) & 3;     // m group (8 m)
    const int ds   = tid >> 7;           // d sub-split (16 d each)
    const int hw   = blockIdx.x * 32 + lane;
    const int dq   = blockIdx.y;
    const int dbase = dq * 64 + ds * 16;

    const float* qp[NB];
#pragma unroll
    for (int b = 0; b < NB; b++)
        qp[b] = g_q + (size_t)b * DK * HW + (size_t)dbase * HW + hw;
    const float* kp[8];
#pragma unroll
    for (int j = 0; j < 8; j++)
        kp[j] = key + (size_t)(ms * 8 + j) * DK * HW + (size_t)dbase * HW + hw;

    float acc[NB][8];
#pragma unroll
    for (int b = 0; b < NB; b++)
#pragma unroll
        for (int j = 0; j < 8; j++) acc[b][j] = 0.0f;

#pragma unroll 2
    for (int d = 0; d < 16; d++) {
        float q0 = qp[0][0], q1 = qp[1][0], q2 = qp[2][0], q3 = qp[3][0];
#pragma unroll
        for (int j = 0; j < 8; j++) {
            const float kv = kp[j][0];
            acc[0][j] += q0 * kv;
            acc[1][j] += q1 * kv;
            acc[2][j] += q2 * kv;
            acc[3][j] += q3 * kv;
        }
#pragma unroll
        for (int b = 0; b < NB; b++) qp[b] += HW;
#pragma unroll
        for (int j = 0; j < 8; j++) kp[j] += HW;
    }

    // stash partials: s_red[ds][m][b][lane]
#pragma unroll
    for (int b = 0; b < NB; b++)
#pragma unroll
        for (int j = 0; j < 8; j++)
            s_red[(((ds * LM) + ms * 8 + j) * NB + b) * 32 + lane] = acc[b][j];
    __syncthreads();

    // reduce ds and write partial: 128 threads = 32 hw x 4 b
    if (tid < 128) {
        const int b   = tid >> 5;
        const int l   = tid & 31;
        const int hwg = blockIdx.x * 32 + l;
        float* pp = g_part + (((size_t)dq * NB + b) * LM) * HW + hwg;
#pragma unroll
        for (int m = 0; m < LM; m++) {
            const float v = s_red[((0 * LM + m) * NB + b) * 32 + l]
                          + s_red[((1 * LM + m) * NB + b) * 32 + l]
                          + s_red[((2 * LM + m) * NB + b) * 32 + l]
                          + s_red[((3 * LM + m) * NB + b) * 32 + l];
            pp[(size_t)m * HW] = v;
        }
    }
}

// ---------------------------------------------------------------------------
// Kernel 2b: finish — sum DQ partials, softmax over m, write g_attn.
// Block 128 = 32 hw x 4 b, grid 128.
// ---------------------------------------------------------------------------
__global__ __launch_bounds__(128) void attn_finish_kernel() {
    const int tid = threadIdx.x;
    const int b   = tid >> 5;
    const int l   = tid & 31;
    const int hw  = blockIdx.x * 32 + l;

    float s[LM];
    float mx = -1e30f;
#pragma unroll
    for (int m = 0; m < LM; m++) {
        float v = 0.0f;
#pragma unroll
        for (int dq = 0; dq < DQ; dq++)
            v += g_part[((((size_t)dq * NB + b) * LM) + m) * HW + hw];
        s[m] = v;
        mx = fmaxf(mx, v);
    }
    float sum = 0.0f;
#pragma unroll
    for (int m = 0; m < LM; m++) { s[m] = __expf(s[m] - mx); sum += s[m]; }
    const float inv = 1.0f / sum;
    float* ap = g_attn + (size_t)b * LM * HW + hw;
#pragma unroll
    for (int m = 0; m < LM; m++) ap[(size_t)m * HW] = s[m] * inv;
}

// ---------------------------------------------------------------------------
// Kernel 3: out[b][c][hw] = fm[b][c][hw] + 0.5*sum_m attn[b][m][hw]*val[m][c][hw]
// EXACT R5/R8 version (best measured: 92.4us, 46% DRAM, minimal traffic).
// Block 256 = 32 hw x 2 batch-groups x 4 hw-subtiles. Each thread handles 2
// batches (attn in 64 regs); val loaded once per pair (register-level reuse).
// Grid (32 hw-tiles, 12 c-chunks of 43).
// ---------------------------------------------------------------------------
__global__ __launch_bounds__(256) void out_kernel(
    const float* __restrict__ fm, const float* __restrict__ val,
    float* __restrict__ out) {
    const int tid  = threadIdx.x;
    const int lane = tid & 31;
    const int bg   = (tid >> 5) & 1;
    const int sub  = tid >> 6;
    const int hw   = blockIdx.x * 128 + sub * 32 + lane;
    const int c0   = blockIdx.y * 43;       // 516 = 12 * 43
    const int b0   = bg * 2;
    const int b1   = b0 + 1;

    float a0[LM], a1[LM];
    {
        const float* ap0 = g_attn + (size_t)b0 * LM * HW + hw;
        const float* ap1 = g_attn + (size_t)b1 * LM * HW + hw;
#pragma unroll
        for (int m = 0; m < LM; m++) {
            a0[m] = ap0[(size_t)m * HW];
            a1[m] = ap1[(size_t)m * HW];
        }
    }

    const float* fmp0 = fm + (size_t)b0 * DV * HW + hw;
    const float* fmp1 = fm + (size_t)b1 * DV * HW + hw;
    float*       op0  = out + (size_t)b0 * DV * HW + hw;
    float*       op1  = out + (size_t)b1 * DV * HW + hw;

#pragma unroll 2
    for (int cc = 0; cc < 43; cc++) {
        const int c = c0 + cc;
        const float* vp = val + (size_t)c * HW + hw;
        float s0 = 0.0f, s1 = 0.0f, t0 = 0.0f, t1 = 0.0f;
#pragma unroll
        for (int m = 0; m < LM; m += 2) {
            const float v0 = vp[(size_t)(m * DV) * HW];
            const float v1 = vp[(size_t)((m + 1) * DV) * HW];
            s0 += a0[m] * v0;     t0 += a1[m] * v0;
            s1 += a0[m + 1] * v1; t1 += a1[m + 1] * v1;
        }
        op0[(size_t)c * HW] = fmp0[(size_t)c * HW] + 0.5f * (s0 + s1);
        op1[(size_t)c * HW] = fmp1[(size_t)c * HW] + 0.5f * (t0 + t1);
    }
}

// ---------------------------------------------------------------------------
// Launch. Inputs (metadata order): fc, fm, key_buffer, value_buffer, Q, K, V.
// concat(new, buffer)[-32:] keeps exactly the buffers -> K and V matrices are
// dead inputs; only q = fc@Q survives.
// ---------------------------------------------------------------------------
extern "C" void kernel_launch(void* const* d_in, const int* in_sizes, int n_in,
                              void* d_out, int out_size) {
    const float* fc   = (const float*)d_in[0];
    const float* fm   = (const float*)d_in[1];
    const float* keyb = (const float*)d_in[2];
    const float* valb = (const float*)d_in[3];
    const float* Qm   = (const float*)d_in[4];
    float* out = (float*)d_out;

    const int red_bytes = DS * LM * NB * 32 * sizeof(float);   // 64KB
    cudaFuncSetAttribute(attn_partial_kernel,
                         cudaFuncAttributeMaxDynamicSharedMemorySize, red_bytes);

    qproj_kernel<<<dim3(HW / 128, DK / 128, NB), 256>>>(fc, Qm);
    attn_partial_kernel<<<dim3(HW / 32, DQ), 512, red_bytes>>>(keyb);
    attn_finish_kernel<<<dim3(HW / 32), 128>>>();
    out_kernel<<<dim3(HW / 128, 12), 256>>>(fm, valb, out);
}

// round 10
// speedup vs baseline: 1.4262x; 1.0404x over previous
#include <cuda_runtime.h>

#define NB 4
#define DK 256
#define DV 516
#define HW 4096
#define LM 32
#define DS 4            // d-splits inside attn block
#define DQ 4            // d-splits across gridDim.y (64 d per block)

#define CCH 14          // out c-chunk: 37 chunks x 32 hw-tiles = 1184 = 4 waves x 296
#define NCH 37

// temp = log2(32*64*64 + 64*64) / sqrt(256)
#define TEMP 1.06527463f

// packed f32x2 FMA: d = a*b + d, lane-wise (2 independent IEEE fp32 fmas)
#define FMA_F32X2(d, a, b) \
    asm("fma.rn.f32x2 %0, %1, %2, %0;" : "+l"(d) : "l"(a), "l"(b))
// duplicate one fp32 into both lanes of a 64-bit packed register
#define PACK_DUP_F32X2(out, f) \
    asm("mov.b64 %0, {%1, %1};" : "=l"(out) : "r"(__float_as_uint(f)))

// Scratch (static device allocations only; no cudaMalloc anywhere)
__device__ float g_q[NB * DK * HW];            // 16 MB: q[b][d][hw], pre-scaled
__device__ float g_attn[NB * LM * HW];         // 2 MB:  attn[b][m][hw]
__device__ float g_part[DQ * NB * LM * HW];    // 8 MB:  partial scores

// ---------------------------------------------------------------------------
// Kernel 1: q[b][d][hw] = TEMP * sum_c Q[c][d] * fc[b][c][hw]
// 128x128 block tile, BK=8, 256 threads, 8x8 register tile, double-buffered
// smem + register fragments, packed fma.rn.f32x2 inner product.
// ---------------------------------------------------------------------------
__global__ __launch_bounds__(256, 2) void qproj_kernel(
    const float* __restrict__ fc, const float* __restrict__ Qm) {
    __shared__ float As[2][8][128];   // [buf][c][d]
    __shared__ float Bs[2][8][128];   // [buf][c][hw]

    const int b   = blockIdx.z;
    const int d0  = blockIdx.y * 128;
    const int hw0 = blockIdx.x * 128;
    const int tid = threadIdx.x;
    const int tx  = tid & 15;        // hw tile coord (x8)
    const int ty  = tid >> 4;        // d  tile coord (x8)

    const float* fcb = fc + (size_t)b * DK * HW;

    const int lr = tid >> 5;          // 0..7  (c within tile)
    const int lc = (tid & 31) * 4;    // 0..124

    // packed accumulators: acc2[i][j2] holds cols (tx*8+2*j2, +1) for row i
    unsigned long long acc2[8][4];
#pragma unroll
    for (int i = 0; i < 8; i++)
#pragma unroll
        for (int j = 0; j < 4; j++) acc2[i][j] = 0ull;   // {0.f, 0.f}

    float4 pa = *(const float4*)(Qm + (size_t)lr * DK + d0 + lc);
    float4 pb = *(const float4*)(fcb + (size_t)lr * HW + hw0 + lc);
    *(float4*)&As[0][lr][lc] = pa;
    *(float4*)&Bs[0][lr][lc] = pb;
    __syncthreads();

    // register fragment double buffer
    float fa[2][8];
    unsigned long long fb[2][4];

    int buf = 0;
    for (int k0 = 0; k0 < DK; k0 += 8) {
        const bool has_next = (k0 + 8) < DK;
        if (has_next) {
            pa = *(const float4*)(Qm + (size_t)(k0 + 8 + lr) * DK + d0 + lc);
            pb = *(const float4*)(fcb + (size_t)(k0 + 8 + lr) * HW + hw0 + lc);
        }

        // preload fragment k=0 of this tile
        *(float4*)(fa[0])     = *(const float4*)&As[buf][0][ty * 8];
        *(float4*)(fa[0] + 4) = *(const float4*)&As[buf][0][ty * 8 + 4];
        {
            ulonglong2 t0 = *(const ulonglong2*)&Bs[buf][0][tx * 8];
            ulonglong2 t1 = *(const ulonglong2*)&Bs[buf][0][tx * 8 + 4];
            fb[0][0] = t0.x; fb[0][1] = t0.y; fb[0][2] = t1.x; fb[0][3] = t1.y;
        }

#pragma unroll
        for (int k = 0; k < 8; k++) {
            const int cur = k & 1;
            const int nxt = cur ^ 1;
            if (k < 7) {   // issue next fragment's LDS before this k's FFMAs
                *(float4*)(fa[nxt])     = *(const float4*)&As[buf][k + 1][ty * 8];
                *(float4*)(fa[nxt] + 4) = *(const float4*)&As[buf][k + 1][ty * 8 + 4];
                ulonglong2 t0 = *(const ulonglong2*)&Bs[buf][k + 1][tx * 8];
                ulonglong2 t1 = *(const ulonglong2*)&Bs[buf][k + 1][tx * 8 + 4];
                fb[nxt][0] = t0.x; fb[nxt][1] = t0.y;
                fb[nxt][2] = t1.x; fb[nxt][3] = t1.y;
            }
#pragma unroll
            for (int i = 0; i < 8; i++) {
                unsigned long long a2;
                PACK_DUP_F32X2(a2, fa[cur][i]);
                FMA_F32X2(acc2[i][0], a2, fb[cur][0]);
                FMA_F32X2(acc2[i][1], a2, fb[cur][1]);
                FMA_F32X2(acc2[i][2], a2, fb[cur][2]);
                FMA_F32X2(acc2[i][3], a2, fb[cur][3]);
            }
        }

        if (has_next) {
            *(float4*)&As[buf ^ 1][lr][lc] = pa;
            *(float4*)&Bs[buf ^ 1][lr][lc] = pb;
            __syncthreads();
            buf ^= 1;
        }
    }

    float* qo = g_q + (size_t)b * DK * HW;
#pragma unroll
    for (int i = 0; i < 8; i++) {
        float* dst = qo + (size_t)(d0 + ty * 8 + i) * HW + hw0 + tx * 8;
        const float* af = (const float*)acc2[i];   // little-endian: low lane first
        float4 v0, v1;
        v0.x = af[0] * TEMP; v0.y = af[1] * TEMP;
        v0.z = af[2] * TEMP; v0.w = af[3] * TEMP;
        v1.x = af[4] * TEMP; v1.y = af[5] * TEMP;
        v1.z = af[6] * TEMP; v1.w = af[7] * TEMP;
        *(float4*)(dst)     = v0;
        *(float4*)(dst + 4) = v1;
    }
}

// ---------------------------------------------------------------------------
// Kernel 2a: partial scores. Grid (HW/32, DQ) = 512 blocks.
// Block 512 = 32 hw lanes x 4 ms (8 m each) x 4 ds (16 d each). Each thread
// computes all 4 batches (key element loaded ONCE; 128B coalesced loads).
// result -> g_part[dq][b][m][hw].
// ---------------------------------------------------------------------------
extern __shared__ float s_red[];   // [DS][LM][NB][32] = 64KB

__global__ __launch_bounds__(512) void attn_partial_kernel(
    const float* __restrict__ key) {
    const int tid  = threadIdx.x;
    const int lane = tid & 31;           // hw
    const int ms   = (tid >> 5) & 3;     // m group (8 m)
    const int ds   = tid >> 7;           // d sub-split (16 d each)
    const int hw   = blockIdx.x * 32 + lane;
    const int dq   = blockIdx.y;
    const int dbase = dq * 64 + ds * 16;

    const float* qp[NB];
#pragma unroll
    for (int b = 0; b < NB; b++)
        qp[b] = g_q + (size_t)b * DK * HW + (size_t)dbase * HW + hw;
    const float* kp[8];
#pragma unroll
    for (int j = 0; j < 8; j++)
        kp[j] = key + (size_t)(ms * 8 + j) * DK * HW + (size_t)dbase * HW + hw;

    float acc[NB][8];
#pragma unroll
    for (int b = 0; b < NB; b++)
#pragma unroll
        for (int j = 0; j < 8; j++) acc[b][j] = 0.0f;

#pragma unroll 2
    for (int d = 0; d < 16; d++) {
        float q0 = qp[0][0], q1 = qp[1][0], q2 = qp[2][0], q3 = qp[3][0];
#pragma unroll
        for (int j = 0; j < 8; j++) {
            const float kv = kp[j][0];
            acc[0][j] += q0 * kv;
            acc[1][j] += q1 * kv;
            acc[2][j] += q2 * kv;
            acc[3][j] += q3 * kv;
        }
#pragma unroll
        for (int b = 0; b < NB; b++) qp[b] += HW;
#pragma unroll
        for (int j = 0; j < 8; j++) kp[j] += HW;
    }

    // stash partials: s_red[ds][m][b][lane]
#pragma unroll
    for (int b = 0; b < NB; b++)
#pragma unroll
        for (int j = 0; j < 8; j++)
            s_red[(((ds * LM) + ms * 8 + j) * NB + b) * 32 + lane] = acc[b][j];
    __syncthreads();

    // reduce ds and write partial: 128 threads = 32 hw x 4 b
    if (tid < 128) {
        const int b   = tid >> 5;
        const int l   = tid & 31;
        const int hwg = blockIdx.x * 32 + l;
        float* pp = g_part + (((size_t)dq * NB + b) * LM) * HW + hwg;
#pragma unroll
        for (int m = 0; m < LM; m++) {
            const float v = s_red[((0 * LM + m) * NB + b) * 32 + l]
                          + s_red[((1 * LM + m) * NB + b) * 32 + l]
                          + s_red[((2 * LM + m) * NB + b) * 32 + l]
                          + s_red[((3 * LM + m) * NB + b) * 32 + l];
            pp[(size_t)m * HW] = v;
        }
    }
}

// ---------------------------------------------------------------------------
// Kernel 2b: finish — sum DQ partials, softmax over m, write g_attn.
// Block 128 = 32 hw x 4 b, grid 128.
// ---------------------------------------------------------------------------
__global__ __launch_bounds__(128) void attn_finish_kernel() {
    const int tid = threadIdx.x;
    const int b   = tid >> 5;
    const int l   = tid & 31;
    const int hw  = blockIdx.x * 32 + l;

    float s[LM];
    float mx = -1e30f;
#pragma unroll
    for (int m = 0; m < LM; m++) {
        float v = 0.0f;
#pragma unroll
        for (int dq = 0; dq < DQ; dq++)
            v += g_part[((((size_t)dq * NB + b) * LM) + m) * HW + hw];
        s[m] = v;
        mx = fmaxf(mx, v);
    }
    float sum = 0.0f;
#pragma unroll
    for (int m = 0; m < LM; m++) { s[m] = __expf(s[m] - mx); sum += s[m]; }
    const float inv = 1.0f / sum;
    float* ap = g_attn + (size_t)b * LM * HW + hw;
#pragma unroll
    for (int m = 0; m < LM; m++) ap[(size_t)m * HW] = s[m] * inv;
}

// ---------------------------------------------------------------------------
// Kernel 3: out[b][c][hw] = fm[b][c][hw] + 0.5*sum_m attn[b][m][hw]*val[m][c][hw]
// Same per-block design as R5/R8 (best measured), BUT re-chunked to kill the
// partial wave: regs=128 -> 2 blocks/SM -> n_conc=296; old grid 384 = 1.3
// waves (88-block starved tail). New grid (32 hw-tiles, 37 c-chunks of 14)
// = 1184 blocks = exactly 4.0 waves. attn rereads rise but are L2-resident
// (attn is 2MB); val/fm/out DRAM traffic unchanged.
// ---------------------------------------------------------------------------
__global__ __launch_bounds__(256) void out_kernel(
    const float* __restrict__ fm, const float* __restrict__ val,
    float* __restrict__ out) {
    const int tid  = threadIdx.x;
    const int lane = tid & 31;
    const int bg   = (tid >> 5) & 1;
    const int sub  = tid >> 6;
    const int hw   = blockIdx.x * 128 + sub * 32 + lane;
    const int c0   = blockIdx.y * CCH;
    const int cend = (c0 + CCH < DV) ? (c0 + CCH) : DV;   // last chunk: 12
    const int b0   = bg * 2;
    const int b1   = b0 + 1;

    float a0[LM], a1[LM];
    {
        const float* ap0 = g_attn + (size_t)b0 * LM * HW + hw;
        const float* ap1 = g_attn + (size_t)b1 * LM * HW + hw;
#pragma unroll
        for (int m = 0; m < LM; m++) {
            a0[m] = ap0[(size_t)m * HW];
            a1[m] = ap1[(size_t)m * HW];
        }
    }

    const float* fmp0 = fm + (size_t)b0 * DV * HW + hw;
    const float* fmp1 = fm + (size_t)b1 * DV * HW + hw;
    float*       op0  = out + (size_t)b0 * DV * HW + hw;
    float*       op1  = out + (size_t)b1 * DV * HW + hw;

#pragma unroll 2
    for (int c = c0; c < cend; c++) {
        const float* vp = val + (size_t)c * HW + hw;
        float s0 = 0.0f, s1 = 0.0f, t0 = 0.0f, t1 = 0.0f;
#pragma unroll
        for (int m = 0; m < LM; m += 2) {
            const float v0 = vp[(size_t)(m * DV) * HW];
            const float v1 = vp[(size_t)((m + 1) * DV) * HW];
            s0 += a0[m] * v0;     t0 += a1[m] * v0;
            s1 += a0[m + 1] * v1; t1 += a1[m + 1] * v1;
        }
        op0[(size_t)c * HW] = fmp0[(size_t)c * HW] + 0.5f * (s0 + s1);
        op1[(size_t)c * HW] = fmp1[(size_t)c * HW] + 0.5f * (t0 + t1);
    }
}

// ---------------------------------------------------------------------------
// Launch. Inputs (metadata order): fc, fm, key_buffer, value_buffer, Q, K, V.
// concat(new, buffer)[-32:] keeps exactly the buffers -> K and V matrices are
// dead inputs; only q = fc@Q survives.
// ---------------------------------------------------------------------------
extern "C" void kernel_launch(void* const* d_in, const int* in_sizes, int n_in,
                              void* d_out, int out_size) {
    const float* fc   = (const float*)d_in[0];
    const float* fm   = (const float*)d_in[1];
    const float* keyb = (const float*)d_in[2];
    const float* valb = (const float*)d_in[3];
    const float* Qm   = (const float*)d_in[4];
    float* out = (float*)d_out;

    const int red_bytes = DS * LM * NB * 32 * sizeof(float);   // 64KB
    cudaFuncSetAttribute(attn_partial_kernel,
                         cudaFuncAttributeMaxDynamicSharedMemorySize, red_bytes);

    qproj_kernel<<<dim3(HW / 128, DK / 128, NB), 256>>>(fc, Qm);
    attn_partial_kernel<<<dim3(HW / 32, DQ), 512, red_bytes>>>(keyb);
    attn_finish_kernel<<<dim3(HW / 32), 128>>>();
    out_kernel<<<dim3(HW / 128, NCH), 256>>>(fm, valb, out);
}

// round 11
// speedup vs baseline: 1.4581x; 1.0224x over previous
#include <cuda_runtime.h>

#define NB 4
#define DK 256
#define DV 516
#define HW 4096
#define LM 32
#define DSP 2           // d sub-splits inside attn block (32 d each)
#define DQ 4            // d-splits across gridDim.y (64 d per block)

#define CCH 14          // out c-chunk: 37 chunks x 32 hw-tiles = 1184 = 4 waves x 296
#define NCH 37

// temp = log2(32*64*64 + 64*64) / sqrt(256)
#define TEMP 1.06527463f

// packed f32x2 FMA: d = a*b + d, lane-wise (2 independent IEEE fp32 fmas)
#define FMA_F32X2(d, a, b) \
    asm("fma.rn.f32x2 %0, %1, %2, %0;" : "+l"(d) : "l"(a), "l"(b))
// duplicate one fp32 into both lanes of a 64-bit packed register
#define PACK_DUP_F32X2(out, f) \
    asm("mov.b64 %0, {%1, %1};" : "=l"(out) : "r"(__float_as_uint(f)))

// Scratch (static device allocations only; no cudaMalloc anywhere)
__device__ float g_q[NB * DK * HW];            // 16 MB: q[b][d][hw], pre-scaled
__device__ float g_attn[NB * LM * HW];         // 2 MB:  attn[b][m][hw]
__device__ float g_part[DQ * NB * LM * HW];    // 8 MB:  partial scores

// ---------------------------------------------------------------------------
// Kernel 1: q[b][d][hw] = TEMP * sum_c Q[c][d] * fc[b][c][hw]
// 128x128 block tile, BK=8, 256 threads, 8x8 register tile, double-buffered
// smem + register fragments, packed fma.rn.f32x2 inner product. (R9 version.)
// ---------------------------------------------------------------------------
__global__ __launch_bounds__(256, 2) void qproj_kernel(
    const float* __restrict__ fc, const float* __restrict__ Qm) {
    __shared__ float As[2][8][128];   // [buf][c][d]
    __shared__ float Bs[2][8][128];   // [buf][c][hw]

    const int b   = blockIdx.z;
    const int d0  = blockIdx.y * 128;
    const int hw0 = blockIdx.x * 128;
    const int tid = threadIdx.x;
    const int tx  = tid & 15;        // hw tile coord (x8)
    const int ty  = tid >> 4;        // d  tile coord (x8)

    const float* fcb = fc + (size_t)b * DK * HW;

    const int lr = tid >> 5;          // 0..7  (c within tile)
    const int lc = (tid & 31) * 4;    // 0..124

    unsigned long long acc2[8][4];
#pragma unroll
    for (int i = 0; i < 8; i++)
#pragma unroll
        for (int j = 0; j < 4; j++) acc2[i][j] = 0ull;

    float4 pa = *(const float4*)(Qm + (size_t)lr * DK + d0 + lc);
    float4 pb = *(const float4*)(fcb + (size_t)lr * HW + hw0 + lc);
    *(float4*)&As[0][lr][lc] = pa;
    *(float4*)&Bs[0][lr][lc] = pb;
    __syncthreads();

    float fa[2][8];
    unsigned long long fb[2][4];

    int buf = 0;
    for (int k0 = 0; k0 < DK; k0 += 8) {
        const bool has_next = (k0 + 8) < DK;
        if (has_next) {
            pa = *(const float4*)(Qm + (size_t)(k0 + 8 + lr) * DK + d0 + lc);
            pb = *(const float4*)(fcb + (size_t)(k0 + 8 + lr) * HW + hw0 + lc);
        }

        *(float4*)(fa[0])     = *(const float4*)&As[buf][0][ty * 8];
        *(float4*)(fa[0] + 4) = *(const float4*)&As[buf][0][ty * 8 + 4];
        {
            ulonglong2 t0 = *(const ulonglong2*)&Bs[buf][0][tx * 8];
            ulonglong2 t1 = *(const ulonglong2*)&Bs[buf][0][tx * 8 + 4];
            fb[0][0] = t0.x; fb[0][1] = t0.y; fb[0][2] = t1.x; fb[0][3] = t1.y;
        }

#pragma unroll
        for (int k = 0; k < 8; k++) {
            const int cur = k & 1;
            const int nxt = cur ^ 1;
            if (k < 7) {
                *(float4*)(fa[nxt])     = *(const float4*)&As[buf][k + 1][ty * 8];
                *(float4*)(fa[nxt] + 4) = *(const float4*)&As[buf][k + 1][ty * 8 + 4];
                ulonglong2 t0 = *(const ulonglong2*)&Bs[buf][k + 1][tx * 8];
                ulonglong2 t1 = *(const ulonglong2*)&Bs[buf][k + 1][tx * 8 + 4];
                fb[nxt][0] = t0.x; fb[nxt][1] = t0.y;
                fb[nxt][2] = t1.x; fb[nxt][3] = t1.y;
            }
#pragma unroll
            for (int i = 0; i < 8; i++) {
                unsigned long long a2;
                PACK_DUP_F32X2(a2, fa[cur][i]);
                FMA_F32X2(acc2[i][0], a2, fb[cur][0]);
                FMA_F32X2(acc2[i][1], a2, fb[cur][1]);
                FMA_F32X2(acc2[i][2], a2, fb[cur][2]);
                FMA_F32X2(acc2[i][3], a2, fb[cur][3]);
            }
        }

        if (has_next) {
            *(float4*)&As[buf ^ 1][lr][lc] = pa;
            *(float4*)&Bs[buf ^ 1][lr][lc] = pb;
            __syncthreads();
            buf ^= 1;
        }
    }

    float* qo = g_q + (size_t)b * DK * HW;
#pragma unroll
    for (int i = 0; i < 8; i++) {
        float* dst = qo + (size_t)(d0 + ty * 8 + i) * HW + hw0 + tx * 8;
        const float* af = (const float*)acc2[i];
        float4 v0, v1;
        v0.x = af[0] * TEMP; v0.y = af[1] * TEMP;
        v0.z = af[2] * TEMP; v0.w = af[3] * TEMP;
        v1.x = af[4] * TEMP; v1.y = af[5] * TEMP;
        v1.z = af[6] * TEMP; v1.w = af[7] * TEMP;
        *(float4*)(dst)     = v0;
        *(float4*)(dst + 4) = v1;
    }
}

// ---------------------------------------------------------------------------
// Kernel 2a v3: partial scores with hw-PAIRS (LDG.64 + native f32x2 FMA).
// Each lane covers 2 adjacent pixels -> q/k float2 loads are naturally packed,
// zero pack movs, all math fma.rn.f32x2. Halves LDG count, FFMA count, and
// pointer-update count vs scalar. d-loop unrolled x4 with literal offsets.
// Block 256 = 32 lanes x 4 ms (8 m) x 2 ds (32 d). Grid (HW/64, DQ) = 256
// blocks at 2/SM = 0.86 waves. smem 64KB.
// ---------------------------------------------------------------------------
__global__ __launch_bounds__(256) void attn_partial_kernel(
    const float* __restrict__ key) {
    extern __shared__ float s_red[];   // [DSP][LM][NB][64] = 64KB

    const int tid  = threadIdx.x;
    const int lane = tid & 31;           // hw pair index
    const int ms   = (tid >> 5) & 3;     // m group (8 m)
    const int ds   = tid >> 7;           // d sub-split (32 d each)
    const int hw2  = blockIdx.x * 64 + lane * 2;
    const int dq   = blockIdx.y;
    const int dbase = dq * 64 + ds * 32;

    const float* qp[NB];
#pragma unroll
    for (int b = 0; b < NB; b++)
        qp[b] = g_q + (size_t)b * DK * HW + (size_t)dbase * HW + hw2;
    const float* kp[8];
#pragma unroll
    for (int j = 0; j < 8; j++)
        kp[j] = key + (size_t)(ms * 8 + j) * DK * HW + (size_t)dbase * HW + hw2;

    unsigned long long acc2[NB][8];
#pragma unroll
    for (int b = 0; b < NB; b++)
#pragma unroll
        for (int j = 0; j < 8; j++) acc2[b][j] = 0ull;

    for (int d = 0; d < 32; d += 4) {
#pragma unroll
        for (int u = 0; u < 4; u++) {
            unsigned long long q2[NB];
#pragma unroll
            for (int b = 0; b < NB; b++)
                q2[b] = *(const unsigned long long*)(qp[b] + u * HW);
#pragma unroll
            for (int j = 0; j < 8; j++) {
                const unsigned long long k2 =
                    *(const unsigned long long*)(kp[j] + u * HW);
                FMA_F32X2(acc2[0][j], q2[0], k2);
                FMA_F32X2(acc2[1][j], q2[1], k2);
                FMA_F32X2(acc2[2][j], q2[2], k2);
                FMA_F32X2(acc2[3][j], q2[3], k2);
            }
        }
#pragma unroll
        for (int b = 0; b < NB; b++) qp[b] += 4 * HW;
#pragma unroll
        for (int j = 0; j < 8; j++) kp[j] += 4 * HW;
    }

    // stash partials: s_red[ds][m][b][2*lane .. 2*lane+1]
#pragma unroll
    for (int b = 0; b < NB; b++)
#pragma unroll
        for (int j = 0; j < 8; j++)
            *(unsigned long long*)
                &s_red[(((ds * LM) + ms * 8 + j) * NB + b) * 64 + 2 * lane] =
                    acc2[b][j];
    __syncthreads();

    // reduce ds and write: 256 threads = 64 hw x 4 b
    {
        const int l   = tid & 63;
        const int b   = tid >> 6;
        const int hwg = blockIdx.x * 64 + l;
        float* pp = g_part + (((size_t)dq * NB + b) * LM) * HW + hwg;
#pragma unroll
        for (int m = 0; m < LM; m++) {
            const float v = s_red[((0 * LM + m) * NB + b) * 64 + l]
                          + s_red[((1 * LM + m) * NB + b) * 64 + l];
            pp[(size_t)m * HW] = v;
        }
    }
}

// ---------------------------------------------------------------------------
// Kernel 2b v2: finish — dq-parallel partial loads, smem reduce, softmax.
// Block 512 = 32 hw x 4 b x 4 dq-threads (4x the in-flight load bytes of v1).
// Grid 128. smem 64KB.
// ---------------------------------------------------------------------------
__global__ __launch_bounds__(512) void attn_finish_kernel() {
    extern __shared__ float sf[];    // [DQ][NB][LM][32] = 64KB

    const int tid = threadIdx.x;
    const int l   = tid & 31;
    const int b   = (tid >> 5) & 3;
    const int dqt = tid >> 7;
    const int hw  = blockIdx.x * 32 + l;

    // load this thread's dq-slice: 32 independent coalesced LDG
    {
        const float* pp = g_part + (((size_t)dqt * NB + b) * LM) * HW + hw;
        float* dst = &sf[((dqt * NB + b) * LM) * 32 + l];
#pragma unroll
        for (int m = 0; m < LM; m++)
            dst[m * 32] = pp[(size_t)m * HW];
    }
    __syncthreads();

    // softmax: 128 threads = 32 hw x 4 b
    if (tid < 128) {
        const int bb  = tid >> 5;
        const int ll  = tid & 31;
        const int hwg = blockIdx.x * 32 + ll;
        float s[LM];
        float mx = -1e30f;
#pragma unroll
        for (int m = 0; m < LM; m++) {
            const float v = sf[((0 * NB + bb) * LM + m) * 32 + ll]
                          + sf[((1 * NB + bb) * LM + m) * 32 + ll]
                          + sf[((2 * NB + bb) * LM + m) * 32 + ll]
                          + sf[((3 * NB + bb) * LM + m) * 32 + ll];
            s[m] = v;
            mx = fmaxf(mx, v);
        }
        float sum = 0.0f;
#pragma unroll
        for (int m = 0; m < LM; m++) { s[m] = __expf(s[m] - mx); sum += s[m]; }
        const float inv = 1.0f / sum;
        float* ap = g_attn + (size_t)bb * LM * HW + hwg;
#pragma unroll
        for (int m = 0; m < LM; m++) ap[(size_t)m * HW] = s[m] * inv;
    }
}

// ---------------------------------------------------------------------------
// Kernel 3: out[b][c][hw] = fm[b][c][hw] + 0.5*sum_m attn[b][m][hw]*val[m][c][hw]
// (R10 version: 2 batches/thread, scalar, 1184 blocks = exactly 4.0 waves.)
// ---------------------------------------------------------------------------
__global__ __launch_bounds__(256) void out_kernel(
    const float* __restrict__ fm, const float* __restrict__ val,
    float* __restrict__ out) {
    const int tid  = threadIdx.x;
    const int lane = tid & 31;
    const int bg   = (tid >> 5) & 1;
    const int sub  = tid >> 6;
    const int hw   = blockIdx.x * 128 + sub * 32 + lane;
    const int c0   = blockIdx.y * CCH;
    const int cend = (c0 + CCH < DV) ? (c0 + CCH) : DV;
    const int b0   = bg * 2;
    const int b1   = b0 + 1;

    float a0[LM], a1[LM];
    {
        const float* ap0 = g_attn + (size_t)b0 * LM * HW + hw;
        const float* ap1 = g_attn + (size_t)b1 * LM * HW + hw;
#pragma unroll
        for (int m = 0; m < LM; m++) {
            a0[m] = ap0[(size_t)m * HW];
            a1[m] = ap1[(size_t)m * HW];
        }
    }

    const float* fmp0 = fm + (size_t)b0 * DV * HW + hw;
    const float* fmp1 = fm + (size_t)b1 * DV * HW + hw;
    float*       op0  = out + (size_t)b0 * DV * HW + hw;
    float*       op1  = out + (size_t)b1 * DV * HW + hw;

#pragma unroll 2
    for (int c = c0; c < cend; c++) {
        const float* vp = val + (size_t)c * HW + hw;
        float s0 = 0.0f, s1 = 0.0f, t0 = 0.0f, t1 = 0.0f;
#pragma unroll
        for (int m = 0; m < LM; m += 2) {
            const float v0 = vp[(size_t)(m * DV) * HW];
            const float v1 = vp[(size_t)((m + 1) * DV) * HW];
            s0 += a0[m] * v0;     t0 += a1[m] * v0;
            s1 += a0[m + 1] * v1; t1 += a1[m + 1] * v1;
        }
        op0[(size_t)c * HW] = fmp0[(size_t)c * HW] + 0.5f * (s0 + s1);
        op1[(size_t)c * HW] = fmp1[(size_t)c * HW] + 0.5f * (t0 + t1);
    }
}

// ---------------------------------------------------------------------------
// Launch. Inputs (metadata order): fc, fm, key_buffer, value_buffer, Q, K, V.
// concat(new, buffer)[-32:] keeps exactly the buffers -> K and V matrices are
// dead inputs; only q = fc@Q survives.
// ---------------------------------------------------------------------------
extern "C" void kernel_launch(void* const* d_in, const int* in_sizes, int n_in,
                              void* d_out, int out_size) {
    const float* fc   = (const float*)d_in[0];
    const float* fm   = (const float*)d_in[1];
    const float* keyb = (const float*)d_in[2];
    const float* valb = (const float*)d_in[3];
    const float* Qm   = (const float*)d_in[4];
    float* out = (float*)d_out;

    const int red_bytes = DSP * LM * NB * 64 * sizeof(float);  // 64KB
    const int fin_bytes = DQ * NB * LM * 32 * sizeof(float);   // 64KB
    cudaFuncSetAttribute(attn_partial_kernel,
                         cudaFuncAttributeMaxDynamicSharedMemorySize, red_bytes);
    cudaFuncSetAttribute(attn_finish_kernel,
                         cudaFuncAttributeMaxDynamicSharedMemorySize, fin_bytes);

    qproj_kernel<<<dim3(HW / 128, DK / 128, NB), 256>>>(fc, Qm);
    attn_partial_kernel<<<dim3(HW / 64, DQ), 256, red_bytes>>>(keyb);
    attn_finish_kernel<<<dim3(HW / 32), 512, fin_bytes>>>();
    out_kernel<<<dim3(HW / 128, NCH), 256>>>(fm, valb, out);
}